// round 2
// baseline (speedup 1.0000x reference)
#include <cuda_runtime.h>

// Problem constants
#define D        64
#define SUBN     256
#define T_LEN    16384
#define ZQ_ELEMS 16777216    // 16*64*16384
#define LOSS_OFF ZQ_ELEMS
#define PERP_OFF (ZQ_ELEMS + 1)
#define IDX_OFF  (ZQ_ELEMS + 2)
#define NHALF    131072      // row pairs: (u, u+NHALF)

// Padded smem row: 68 floats; odd j-half (j>=128) skewed +8 floats so the
// 2-way broadcast (lane parity selects j-half) never bank-conflicts.
#define EROW(j)  ((j) * 68 + (((j) >> 7) << 3))
#define E_FLOATS (256 * 68 + 8)

// Persistent scratch. Invariant: zero at kernel_launch entry.
// Zero-initialized at module load; vq_finalize re-zeros after reading.
__device__ int    g_counts[SUBN];
__device__ double g_sse;

// ---- packed fp32x2 FMA (FFMA2) ----
__device__ __forceinline__ unsigned long long ffma2(unsigned long long a,
                                                    unsigned long long b,
                                                    unsigned long long c) {
    unsigned long long d;
    asm("fma.rn.f32x2 %0, %1, %2, %3;" : "=l"(d) : "l"(a), "l"(b), "l"(c));
    return d;
}
__device__ __forceinline__ float2 unpack2(unsigned long long v) {
    float2 r;
    asm("mov.b64 {%0, %1}, %2;" : "=f"(r.x), "=f"(r.y) : "l"(v));
    return r;
}

// ------------------------------------------------------------------
// Main persistent kernel: grid = #SMs, 256 threads.
// Lane pair (l, l^1) handles rows (u, u+NHALF); lane parity picks j-half.
// ------------------------------------------------------------------
__global__ __launch_bounds__(256, 1) void vq_main(const float* __restrict__ z,
                                                  const float* __restrict__ one_hot,
                                                  const float* __restrict__ W,
                                                  float* __restrict__ out) {
    extern __shared__ float smem[];
    float* E_sp  = smem;                       // [E_FLOATS]
    float* sEE   = smem + E_FLOATS;            // [256]
    int*   shist = (int*)(sEE + SUBN);         // [256]
    float* sred  = (float*)(shist + SUBN);     // [8]

    const int tid = threadIdx.x;

    // pos = argmax(one_hot), first-max semantics
    float m = one_hot[0];
    int pos = 0;
    #pragma unroll
    for (int i = 1; i < 7; i++) {
        float v = one_hot[i];
        if (v > m) { m = v; pos = i; }
    }

    // Load selected 256x64 codebook into skewed/padded smem
    const float4* Wsrc = (const float4*)(W + (size_t)pos * SUBN * D);
    #pragma unroll 4
    for (int i = tid; i < SUBN * D / 4; i += 256) {
        int row = i >> 4;
        int k4  = i & 15;
        *(float4*)&E_sp[EROW(row) + k4 * 4] = Wsrc[i];
    }
    shist[tid] = 0;
    __syncthreads();

    // ||E_j||^2 (sub-rounding here is ~1e-13 abs, irrelevant to argmin)
    {
        const float* er = &E_sp[EROW(tid)];
        float s = 0.f;
        #pragma unroll
        for (int k = 0; k < D; k++) s = fmaf(er[k], er[k], s);
        sEE[tid] = s;
    }
    __syncthreads();

    const int half  = tid & 1;
    const int jbase = half << 7;               // 0 or 128
    const int gtid  = blockIdx.x * 256 + tid;
    const int pair0 = gtid >> 1;
    const int stride = gridDim.x * 128;        // pairs per chip pass
    const int niter  = (NHALF + stride - 1) / stride;  // uniform for all threads

    float sse_loc = 0.f;

    for (int it = 0; it < niter; it++) {
        const int u   = pair0 + it * stride;
        const bool act = (u < NHALF);
        const int uc  = act ? u : 0;

        const int r0 = uc;
        const int r1 = uc + NHALF;

        // Load both z rows packed as f32x2; ||z||^2 exactly as R1 (single chain)
        const ulonglong2* zp0 = (const ulonglong2*)(z + (size_t)r0 * D);
        const ulonglong2* zp1 = (const ulonglong2*)(z + (size_t)r1 * D);
        unsigned long long za[32], zb[32];
        unsigned long long zza = 0ull, zzb = 0ull;
        #pragma unroll
        for (int i = 0; i < 16; i++) {
            ulonglong2 v = zp0[i];
            za[2 * i] = v.x; za[2 * i + 1] = v.y;
            zza = ffma2(v.x, v.x, zza);
            zza = ffma2(v.y, v.y, zza);
        }
        #pragma unroll
        for (int i = 0; i < 16; i++) {
            ulonglong2 v = zp1[i];
            zb[2 * i] = v.x; zb[2 * i + 1] = v.y;
            zzb = ffma2(v.x, v.x, zzb);
            zzb = ffma2(v.y, v.y, zzb);
        }
        float2 p;
        p = unpack2(zza); const float zz0 = p.x + p.y;
        p = unpack2(zzb); const float zz1 = p.x + p.y;

        float besta = 3.402823466e38f, bestb = 3.402823466e38f;
        int   bja = jbase, bjb = jbase;

        #pragma unroll 2
        for (int j2 = 0; j2 < 128; j2++) {
            const int j = jbase + j2;
            const ulonglong2* ej = (const ulonglong2*)&E_sp[EROW(j)];
            unsigned long long a0 = 0ull, a1 = 0ull, b0 = 0ull, b1 = 0ull;
            #pragma unroll
            for (int i = 0; i < 16; i++) {
                ulonglong2 e = ej[i];
                a0 = ffma2(za[2 * i],     e.x, a0);
                a1 = ffma2(za[2 * i + 1], e.y, a1);
                b0 = ffma2(zb[2 * i],     e.x, b0);
                b1 = ffma2(zb[2 * i + 1], e.y, b1);
            }
            float2 x0 = unpack2(a0), x1 = unpack2(a1);
            float2 y0 = unpack2(b0), y1 = unpack2(b1);
            const float dota = (x0.x + x0.y) + (x1.x + x1.y);
            const float dotb = (y0.x + y0.y) + (y1.x + y1.y);
            const float ee   = sEE[j];
            const float dca  = (zz0 + ee) - 2.0f * dota;
            const float dcb  = (zz1 + ee) - 2.0f * dotb;
            if (dca < besta) { besta = dca; bja = j; }  // strict <: first index
            if (dcb < bestb) { bestb = dcb; bjb = j; }
        }

        // Combine the two j-halves across the lane pair (tie -> smaller j)
        {
            float ob = __shfl_xor_sync(0xffffffffu, besta, 1);
            int   oj = __shfl_xor_sync(0xffffffffu, bja,   1);
            if (ob < besta || (ob == besta && oj < bja)) { besta = ob; bja = oj; }
            ob = __shfl_xor_sync(0xffffffffu, bestb, 1);
            oj = __shfl_xor_sync(0xffffffffu, bjb,   1);
            if (ob < bestb || (ob == bestb && oj < bjb)) { bestb = ob; bjb = oj; }
        }

        if (act) {
            if (half == 0) {
                atomicAdd(&shist[bja], 1);
                atomicAdd(&shist[bjb], 1);
                sse_loc += besta + bestb;       // best == ||z - e||^2
                out[IDX_OFF + r0] = (float)bja;
                out[IDX_OFF + r1] = (float)bjb;
            }
            // z_q transposed write: each lane writes its 32 d-components
            const int b0i = r0 >> 14, t0 = r0 & (T_LEN - 1);
            const int b1i = r1 >> 14, t1 = r1 & (T_LEN - 1);
            float* o0 = out + (size_t)b0i * D * T_LEN + t0;
            float* o1 = out + (size_t)b1i * D * T_LEN + t1;
            const float* ea = &E_sp[EROW(bja)];
            const float* eb = &E_sp[EROW(bjb)];
            const int dbase = half << 5;
            #pragma unroll
            for (int d0 = 0; d0 < 32; d0 += 4) {
                float4 v = *(const float4*)&ea[dbase + d0];
                o0[(size_t)(dbase + d0 + 0) * T_LEN] = v.x;
                o0[(size_t)(dbase + d0 + 1) * T_LEN] = v.y;
                o0[(size_t)(dbase + d0 + 2) * T_LEN] = v.z;
                o0[(size_t)(dbase + d0 + 3) * T_LEN] = v.w;
                float4 w = *(const float4*)&eb[dbase + d0];
                o1[(size_t)(dbase + d0 + 0) * T_LEN] = w.x;
                o1[(size_t)(dbase + d0 + 1) * T_LEN] = w.y;
                o1[(size_t)(dbase + d0 + 2) * T_LEN] = w.z;
                o1[(size_t)(dbase + d0 + 3) * T_LEN] = w.w;
            }
        }
    }

    // Block-reduce sse, flush histogram
    float s = sse_loc;
    #pragma unroll
    for (int o = 16; o > 0; o >>= 1)
        s += __shfl_down_sync(0xffffffffu, s, o);
    if ((tid & 31) == 0) sred[tid >> 5] = s;
    __syncthreads();
    if (tid == 0) {
        float tot = 0.f;
        #pragma unroll
        for (int w = 0; w < 8; w++) tot += sred[w];
        atomicAdd(&g_sse, (double)tot);
    }
    atomicAdd(&g_counts[tid], shist[tid]);
}

// ------------------------------------------------------------------
// Finalize: loss + perplexity, then reset accumulators for next replay
// ------------------------------------------------------------------
__global__ void vq_finalize(float* __restrict__ out) {
    __shared__ float sw[8];
    int tid = threadIdx.x;          // 256 threads
    float c  = (float)g_counts[tid];
    g_counts[tid] = 0;              // restore zero-invariant
    float em = c * (1.0f / 262144.0f);
    float v  = em * logf(em + 1e-10f);

    #pragma unroll
    for (int o = 16; o > 0; o >>= 1)
        v += __shfl_down_sync(0xffffffffu, v, o);
    if ((tid & 31) == 0) sw[tid >> 5] = v;
    __syncthreads();
    if (tid == 0) {
        float H = 0.f;
        #pragma unroll
        for (int w = 0; w < 8; w++) H += sw[w];
        out[PERP_OFF] = expf(-H);
        double sse = g_sse;
        g_sse = 0.0;                // restore zero-invariant
        float m = (float)(sse * (1.0 / 16777216.0));
        out[LOSS_OFF] = 0.25f * m + m;   // BETA*mse + mse
    }
}

// ------------------------------------------------------------------
extern "C" void kernel_launch(void* const* d_in, const int* in_sizes, int n_in,
                              void* d_out, int out_size) {
    const float* z       = (const float*)d_in[0];
    const float* one_hot = (const float*)d_in[1];
    const float* W       = (const float*)d_in[2];
    float* out           = (float*)d_out;

    static int nsm = 0;
    if (nsm == 0) {
        cudaDeviceGetAttribute(&nsm, cudaDevAttrMultiProcessorCount, 0);
        if (nsm <= 0) nsm = 148;
        int smem_bytes = (E_FLOATS + SUBN + SUBN + 8) * 4;
        cudaFuncSetAttribute(vq_main, cudaFuncAttributeMaxDynamicSharedMemorySize,
                             smem_bytes);
    }
    const int smem_bytes = (E_FLOATS + SUBN + SUBN + 8) * 4;

    vq_main<<<nsm, 256, smem_bytes>>>(z, one_hot, W, out);
    vq_finalize<<<1, 256>>>(out);
}